// round 6
// baseline (speedup 1.0000x reference)
#include <cuda_runtime.h>
#include <math.h>

#define NPTS 50000
#define S    16
#define C    96
#define CP   97    // padded row: bank-conflict-free [s][*] access
#define G    6
#define CG   16    // C / G
#define TP   32    // points per block in k1
#define TPP  36    // padded point dim in transposed feat tile
#define QKP  100   // padded q/k tile row in k1
#define P    4     // points per block in k2

// ---- scratch (no allocations allowed; __device__ globals are the sanctioned path)
__device__ float d_v [NPTS * C];   // v = feat@Wv + bv
__device__ float d_qW[NPTS * G];   // q @ Ww1
__device__ float d_kW[NPTS * G];   // k @ Ww1
__device__ float d_Wp2w1[C * G];   // Wp2 @ Ww1 (folded)
__device__ float d_bp2w1[G];       // bp2 @ Ww1 (folded)

__device__ __forceinline__ float bn_scale(float g) {
    return g * rsqrtf(1.0f + 1e-5f);
}
__device__ __forceinline__ unsigned long long pack2(float lo, float hi) {
    unsigned long long r;
    asm("mov.b64 %0, {%1, %2};" : "=l"(r) : "r"(__float_as_uint(lo)), "r"(__float_as_uint(hi)));
    return r;
}
__device__ __forceinline__ unsigned long long bcast2(float v) {
    unsigned long long r;
    asm("mov.b64 %0, {%1, %1};" : "=l"(r) : "r"(__float_as_uint(v)));
    return r;
}
__device__ __forceinline__ void unpack2(unsigned long long v, float& lo, float& hi) {
    unsigned l, h;
    asm("mov.b64 {%0, %1}, %2;" : "=r"(l), "=r"(h) : "l"(v));
    lo = __uint_as_float(l); hi = __uint_as_float(h);
}
#define FMA2(acc, a, b) asm("fma.rn.f32x2 %0, %1, %2, %0;" : "+l"(acc) : "l"(a), "l"(b))

// ---------------------------------------------------------------------------
// Kernel 0: fold Wp2@Ww1 and bp2@Ww1 (tiny, one block)
// ---------------------------------------------------------------------------
__global__ void k0_fold(const float* __restrict__ Wp2,
                        const float* __restrict__ bp2,
                        const float* __restrict__ Ww1) {
    int t = threadIdx.x;
    if (t < C * G) {
        int j = t / G, g = t % G;
        float acc = 0.f;
        #pragma unroll 8
        for (int c = 0; c < C; c++) acc += Wp2[j * C + c] * Ww1[c * G + g];
        d_Wp2w1[j * G + g] = acc;
    } else if (t < C * G + G) {
        int g = t - C * G;
        float acc = 0.f;
        for (int c = 0; c < C; c++) acc += bp2[c] * Ww1[c * G + g];
        d_bp2w1[g] = acc;
    }
}

// ---------------------------------------------------------------------------
// Kernel 1: point-tiled fused QKV GEMM with packed f32x2 FMA.
// 288 threads; thread owns one output column of [Wq|Wk|Wv]. Feat tile stored
// channel-major so point-pairs load as b64 (LDS.128 -> ulonglong2, no repack);
// weight broadcast-packed once per channel.
// ---------------------------------------------------------------------------
__global__ __launch_bounds__(288)
void k1_qkv(const float* __restrict__ feat, int n,
            const float* __restrict__ Wq, const float* __restrict__ bq,
            const float* __restrict__ gq, const float* __restrict__ betaq,
            const float* __restrict__ Wk, const float* __restrict__ bk,
            const float* __restrict__ gk, const float* __restrict__ betak,
            const float* __restrict__ Wv, const float* __restrict__ bv,
            const float* __restrict__ Ww1) {
    int base = blockIdx.x * TP;
    int t = threadIdx.x;

    __shared__ __align__(16) float fsh2[C][TPP];   // 13.8 KB transposed feat
    __shared__ float qk[2][TP][QKP];               // 25.6 KB post-bn-relu q,k

    for (int e = t; e < TP * C; e += 288) {
        int p = e / C, c = e % C;
        int row = base + p; if (row >= n) row = n - 1;
        fsh2[c][p] = feat[row * C + c];
    }
    __syncthreads();

    int m  = t / C;        // 0=q, 1=k, 2=v
    int cc = t % C;
    const float* Wm = (m == 0) ? Wq : (m == 1) ? Wk : Wv;

    unsigned long long acc2[TP / 2];
    #pragma unroll
    for (int pp = 0; pp < TP / 2; pp++) acc2[pp] = 0ull;

    #pragma unroll 4
    for (int i = 0; i < C; i++) {
        unsigned long long w2 = bcast2(Wm[i * C + cc]);
        const ulonglong2* frow = (const ulonglong2*)&fsh2[i][0];
        #pragma unroll
        for (int q4 = 0; q4 < TP / 4; q4++) {
            ulonglong2 f = frow[q4];   // LDS.128: 4 points, channel i (broadcast)
            FMA2(acc2[q4 * 2    ], f.x, w2);
            FMA2(acc2[q4 * 2 + 1], f.y, w2);
        }
    }

    if (m == 2) {
        float bias = bv[cc];
        #pragma unroll
        for (int pp = 0; pp < TP / 2; pp++) {
            float lo, hi; unpack2(acc2[pp], lo, hi);
            int r0 = base + 2 * pp, r1 = r0 + 1;
            if (r0 < n) d_v[r0 * C + cc] = lo + bias;
            if (r1 < n) d_v[r1 * C + cc] = hi + bias;
        }
    } else {
        float bb = (m == 0) ? bq[cc] : bk[cc];
        float sc = bn_scale((m == 0) ? gq[cc] : gk[cc]);
        float be = (m == 0) ? betaq[cc] : betak[cc];
        #pragma unroll
        for (int pp = 0; pp < TP / 2; pp++) {
            float lo, hi; unpack2(acc2[pp], lo, hi);
            qk[m][2 * pp    ][cc] = fmaxf(fmaf(lo + bb, sc, be), 0.f);
            qk[m][2 * pp + 1][cc] = fmaxf(fmaf(hi + bb, sc, be), 0.f);
        }
    }
    __syncthreads();

    for (int e = t; e < 2 * TP * G; e += 288) {
        int mm  = e / (TP * G);
        int rem = e % (TP * G);
        int p = rem / G, g = rem % G;
        float a = 0.f;
        #pragma unroll 8
        for (int i = 0; i < C; i += 4) {
            float4 qv = *(const float4*)&qk[mm][p][i];
            a = fmaf(qv.x, Ww1[(i    ) * G + g], a);
            a = fmaf(qv.y, Ww1[(i + 1) * G + g], a);
            a = fmaf(qv.z, Ww1[(i + 2) * G + g], a);
            a = fmaf(qv.w, Ww1[(i + 3) * G + g], a);
        }
        int row = base + p;
        if (row < n) {
            if (mm == 0) d_qW[row * G + g] = a;
            else         d_kW[row * G + g] = a;
        }
    }
}

// ---------------------------------------------------------------------------
// Kernel 2: attention + aggregation. P=4 points per block, 256 threads.
// Packed f32x2 in phases 4, 5 (g-pairs) and 8 (point-pairs via Hg[G][C][P]).
// ---------------------------------------------------------------------------
__global__ __launch_bounds__(256)
void k2_main(const float* __restrict__ coord,
             const int*   __restrict__ ref, int n,
             const float* __restrict__ Wp1, const float* __restrict__ bp1,
             const float* __restrict__ gp,  const float* __restrict__ betap,
             const float* __restrict__ Wp2, const float* __restrict__ bp2,
             const float* __restrict__ bw1, const float* __restrict__ gw,
             const float* __restrict__ betaw,
             const float* __restrict__ Ww2, const float* __restrict__ bw2,
             float* __restrict__ out) {
    int nb = blockIdx.x * P;
    int t  = threadIdx.x;

    __shared__ float hsh[P][S][CP];              // 24.8 KB  relu(bn(pos@Wp1))
    __shared__ __align__(16) float Hg[G * C * P];//  9.2 KB  [g][j][p] point-major
    __shared__ __align__(16) float Wsh[C * G];   //  2.3 KB  folded Wp2@Ww1
    __shared__ float sWp1[3][C];
    __shared__ float sA[C], sB[C];               // bn affine for pos-MLP layer1
    __shared__ __align__(8) float sWw2[G * G];   // staged Ww2 (rows 8B-aligned? G=6 -> see note)
    __shared__ float sGw[G], sBw[G];             // bn affine for weight-enc layer1
    __shared__ float sBw2[G], sBw1c[G];          // bw2; bw1+bp2w1 combined
    __shared__ float pos[P][S][3];
    __shared__ int   idxsh[P][S];
    __shared__ float msk[P][S];
    __shared__ float kWsh[P][S][G];
    __shared__ float Ash [P][S][G];
    __shared__ float wsh [P][S][G];
    __shared__ float wsum[P][G];
    __shared__ float qWsh[P][G];
    __shared__ float c0[P][3];

    // ---- phase 1: indices + weight staging
    if (t < P * S) {
        int p = t / S, s = t % S;
        int row = nb + p; if (row >= n) row = n - 1;
        int id = ref[row * S + s];
        idxsh[p][s] = id;
        int ip1 = id + 1;
        msk[p][s] = (float)((ip1 > 0) - (ip1 < 0));
    }
    if (t >= 64 && t < 64 + P * 3) {
        int e = t - 64, p = e / 3, d = e % 3;
        int row = nb + p; if (row >= n) row = n - 1;
        c0[p][d] = coord[row * 3 + d];
    }
    if (t >= 96 && t < 96 + P * G) {
        int e = t - 96, p = e / G, g = e % G;
        int row = nb + p; if (row >= n) row = n - 1;
        qWsh[p][g] = d_qW[row * G + g];
    }
    if (t >= 128 && t < 128 + G) {
        int g = t - 128;
        sGw[g]   = bn_scale(gw[g]);
        sBw[g]   = betaw[g];
        sBw2[g]  = bw2[g];
        sBw1c[g] = d_bp2w1[g] + bw1[g];
    }
    if (t >= 160 && t < 160 + G * G) {
        int e = t - 160;
        sWw2[e] = Ww2[e];
    }
    for (int e = t; e < C * G; e += 256) Wsh[e] = d_Wp2w1[e];
    if (t < C) {
        float sc = bn_scale(gp[t]);
        sA[t] = sc;
        sB[t] = fmaf(bp1[t], sc, betap[t]);
        sWp1[0][t] = Wp1[0 * C + t];
        sWp1[1][t] = Wp1[1 * C + t];
        sWp1[2][t] = Wp1[2 * C + t];
    }
    __syncthreads();

    // ---- phase 2: pos + kW gathers
    if (t < P * S * 3) {
        int p = t / (S * 3), rem = t % (S * 3), s = rem / 3, d = rem % 3;
        pos[p][s][d] = coord[idxsh[p][s] * 3 + d] - c0[p][d];
    }
    for (int e = t; e < P * S * G; e += 256) {
        int p = e / (S * G), rem = e % (S * G), s = rem / G, g = rem % G;
        kWsh[p][s][g] = d_kW[idxsh[p][s] * G + g];
    }
    __syncthreads();

    // ---- phase 3: h = relu(bn(pos@Wp1))
    for (int e = t; e < P * S * C; e += 256) {
        int p = e / (S * C), rem = e % (S * C), s = rem / C, c = rem % C;
        float a = fmaf(pos[p][s][0], sWp1[0][c],
                  fmaf(pos[p][s][1], sWp1[1][c],
                       pos[p][s][2] * sWp1[2][c]));
        hsh[p][s][c] = fmaxf(fmaf(a, sA[c], sB[c]), 0.f);
    }
    __syncthreads();

    // ---- phase 4: relation@Ww1 (folded) -> bn -> relu, g-pairs packed
    if (t < P * S * (G / 2)) {       // 192 threads, single shot
        int p = t / (S * 3), rem = t % (S * 3), s = rem / 3, gp2 = rem % 3;
        int g0 = gp2 * 2, g1 = g0 + 1;
        unsigned long long u2 = pack2(
            kWsh[p][s][g0] - qWsh[p][g0] + sBw1c[g0],
            kWsh[p][s][g1] - qWsh[p][g1] + sBw1c[g1]);
        const float* hrow = hsh[p][s];
        #pragma unroll 8
        for (int j = 0; j < C; j++) {
            unsigned long long h2 = bcast2(hrow[j]);
            unsigned long long w2 = *(const unsigned long long*)&Wsh[j * G + g0]; // 8B-aligned: 24j+{0,8,16}
            FMA2(u2, h2, w2);
        }
        float u0, u1; unpack2(u2, u0, u1);
        Ash[p][s][g0] = fmaxf(fmaf(u0, sGw[g0], sBw[g0]), 0.f);
        Ash[p][s][g1] = fmaxf(fmaf(u1, sGw[g1], sBw[g1]), 0.f);
    }
    __syncthreads();

    // ---- phase 5: logits = A @ Ww2 + bw2, g2-pairs packed
    if (t < P * S * (G / 2)) {       // 192 threads, single shot
        int p = t / (S * 3), rem = t % (S * 3), s = rem / 3, gp2 = rem % 3;
        int g0 = gp2 * 2, g1 = g0 + 1;
        unsigned long long l2 = pack2(sBw2[g0], sBw2[g1]);
        const float* arow = Ash[p][s];
        #pragma unroll
        for (int g = 0; g < G; g++) {
            unsigned long long a2 = bcast2(arow[g]);
            // sWw2 row g, cols {g0,g1}: byte offset 24g + 8*gp2 -> 8B-aligned LDS.64
            unsigned long long w2 = *(const unsigned long long*)&sWw2[g * G + g0];
            FMA2(l2, a2, w2);
        }
        float l0, l1; unpack2(l2, l0, l1);
        wsh[p][s][g0] = l0;
        wsh[p][s][g1] = l1;
    }
    __syncthreads();

    // ---- phase 6: softmax over neighbours + mask
    if (t < P * G) {
        int p = t / G, g = t % G;
        float m = -1e30f;
        #pragma unroll
        for (int s = 0; s < S; s++) m = fmaxf(m, wsh[p][s][g]);
        float sum = 0.f;
        #pragma unroll
        for (int s = 0; s < S; s++) { float e = __expf(wsh[p][s][g] - m); wsh[p][s][g] = e; sum += e; }
        float inv = 1.0f / sum;
        float ws = 0.f;
        #pragma unroll
        for (int s = 0; s < S; s++) {
            float wv = wsh[p][s][g] * inv * msk[p][s];
            wsh[p][s][g] = wv; ws += wv;
        }
        wsum[p][g] = ws;
    }
    __syncthreads();

    // ---- phase 7: Hg[g][j][p] = sum_s w[p,s,g]*h[p,s,j]  (point-major layout)
    for (int e = t; e < G * C; e += 256) {
        int g = e / C, j = e % C;
        float4 acc = make_float4(0.f, 0.f, 0.f, 0.f);
        #pragma unroll
        for (int s = 0; s < S; s++) {
            acc.x = fmaf(wsh[0][s][g], hsh[0][s][j], acc.x);
            acc.y = fmaf(wsh[1][s][g], hsh[1][s][j], acc.y);
            acc.z = fmaf(wsh[2][s][g], hsh[2][s][j], acc.z);
            acc.w = fmaf(wsh[3][s][g], hsh[3][s][j], acc.w);
        }
        *(float4*)&Hg[(g * C + j) * P] = acc;   // STS.128
    }
    __syncthreads();

    // ---- phase 8: out = v-term + Hg@Wp2 + bp2*wsum, point-pairs packed
    if (t < 2 * C) {
        int pp = t / C, c = t % C;
        int g = c / CG;
        int p0 = pp * 2, p1 = pp * 2 + 1;
        unsigned long long a2 = pack2(bp2[c] * wsum[p0][g], bp2[c] * wsum[p1][g]);
        #pragma unroll 8
        for (int j = 0; j < C; j++) {
            unsigned long long w2 = bcast2(Wp2[j * C + c]);
            unsigned long long h2 = *(const unsigned long long*)&Hg[(g * C + j) * P + p0]; // 8B-aligned (p0 even)
            FMA2(a2, h2, w2);
        }
        float a0, a1; unpack2(a2, a0, a1);
        #pragma unroll
        for (int s = 0; s < S; s++) {
            a0 = fmaf(wsh[p0][s][g], d_v[idxsh[p0][s] * C + c], a0);
            a1 = fmaf(wsh[p1][s][g], d_v[idxsh[p1][s] * C + c], a1);
        }
        int r0 = nb + p0, r1 = nb + p1;
        if (r0 < n) out[r0 * C + c] = a0;
        if (r1 < n) out[r1 * C + c] = a1;
    }
}

// ---------------------------------------------------------------------------
extern "C" void kernel_launch(void* const* d_in, const int* in_sizes, int n_in,
                              void* d_out, int out_size) {
    const float* feat   = (const float*)d_in[0];
    const float* coord  = (const float*)d_in[1];
    const int*   refidx = (const int*)  d_in[2];
    const float* Wq = (const float*)d_in[3];  const float* bq = (const float*)d_in[4];
    const float* gq = (const float*)d_in[5];  const float* betaq = (const float*)d_in[6];
    const float* Wk = (const float*)d_in[7];  const float* bk = (const float*)d_in[8];
    const float* gk = (const float*)d_in[9];  const float* betak = (const float*)d_in[10];
    const float* Wv = (const float*)d_in[11]; const float* bv = (const float*)d_in[12];
    const float* Wp1 = (const float*)d_in[13]; const float* bp1 = (const float*)d_in[14];
    const float* gp  = (const float*)d_in[15]; const float* betap = (const float*)d_in[16];
    const float* Wp2 = (const float*)d_in[17]; const float* bp2 = (const float*)d_in[18];
    const float* Ww1 = (const float*)d_in[19]; const float* bw1 = (const float*)d_in[20];
    const float* gw  = (const float*)d_in[21]; const float* betaw = (const float*)d_in[22];
    const float* Ww2 = (const float*)d_in[23]; const float* bw2 = (const float*)d_in[24];
    float* out = (float*)d_out;

    int n = in_sizes[0] / C;   // 50000

    k0_fold<<<1, C * G + 32>>>(Wp2, bp2, Ww1);
    k1_qkv<<<(n + TP - 1) / TP, 288>>>(feat, n, Wq, bq, gq, betaq,
                                       Wk, bk, gk, betak, Wv, bv, Ww1);
    k2_main<<<(n + P - 1) / P, 256>>>(coord, refidx, n, Wp1, bp1, gp, betap,
                                      Wp2, bp2, bw1, gw, betaw, Ww2, bw2, out);
}